// round 12
// baseline (speedup 1.0000x reference)
#include <cuda_runtime.h>
#include <cuda_bf16.h>
#include <cstdint>
#include <math.h>

#define BB 2
#define TT 2048
#define DIMN 1024
#define HEADS 16
#define DH 64
#define INNER 1024
#define RR 8
#define NT (BB*TT)
#define LORA_SCALE 0.25f
#define EPS_LN 1e-5f

// ---------------- static scratch -------------------------------------------
__device__ float g_xn[NT*DIMN];
__device__ float g_mn[NT*DIMN];
__device__ float g_ao[NT*INNER];
__device__ float g_low[3*NT*RR];
__device__ float g_gateo[NT*RR];
__device__ float g_lowo[NT*RR];
__device__ __nv_bfloat16 g_xhi[NT*DIMN];
__device__ __nv_bfloat16 g_xlo[NT*DIMN];
__device__ __nv_bfloat16 g_whi4[4*DIMN*INNER];
__device__ __nv_bfloat16 g_wlo4[4*DIMN*INNER];
__device__ __nv_bfloat16 g_qhi[NT*INNER];
__device__ __nv_bfloat16 g_qlo[NT*INNER];
__device__ __nv_bfloat16 g_khi[NT*INNER];
__device__ __nv_bfloat16 g_klo[NT*INNER];
__device__ __nv_bfloat16 g_vhi[NT*INNER];
__device__ __nv_bfloat16 g_vlo[NT*INNER];
__device__ __nv_bfloat16 g_aohi[NT*INNER];
__device__ __nv_bfloat16 g_aolo[NT*INNER];

// ---------------- helpers --------------------------------------------------
__device__ __forceinline__ uint32_t smem_u32(const void* p){
    uint32_t a;
    asm("{ .reg .u64 t; cvta.to.shared.u64 t, %1; cvt.u32.u64 %0, t; }" : "=r"(a) : "l"(p));
    return a;
}
#define CP16(sm, g) asm volatile("cp.async.cg.shared.global [%0], [%1], 16;" :: "r"(sm), "l"(g) : "memory")
#define CP_COMMIT() asm volatile("cp.async.commit_group;" ::: "memory")
#define CP_WAIT(n)  asm volatile("cp.async.wait_group %0;" :: "n"(n) : "memory")

__device__ __forceinline__ void ldsm4(uint32_t* r, uint32_t a){
    asm volatile("ldmatrix.sync.aligned.m8n8.x4.shared.b16 {%0,%1,%2,%3}, [%4];"
        : "=r"(r[0]),"=r"(r[1]),"=r"(r[2]),"=r"(r[3]) : "r"(a));
}
__device__ __forceinline__ void ldsm4t(uint32_t* r, uint32_t a){
    asm volatile("ldmatrix.sync.aligned.m8n8.x4.trans.shared.b16 {%0,%1,%2,%3}, [%4];"
        : "=r"(r[0]),"=r"(r[1]),"=r"(r[2]),"=r"(r[3]) : "r"(a));
}
__device__ __forceinline__ void mma_bf16(float* c, const uint32_t* a, uint32_t b0, uint32_t b1){
    asm volatile("mma.sync.aligned.m16n8k16.row.col.f32.bf16.bf16.f32 "
        "{%0,%1,%2,%3}, {%4,%5,%6,%7}, {%8,%9}, {%0,%1,%2,%3};"
        : "+f"(c[0]),"+f"(c[1]),"+f"(c[2]),"+f"(c[3])
        : "r"(a[0]),"r"(a[1]),"r"(a[2]),"r"(a[3]),"r"(b0),"r"(b1));
}
__device__ __forceinline__ void split2(float f0, float f1, uint32_t& hi, uint32_t& lo){
    __nv_bfloat16 h0 = __float2bfloat16_rn(f0);
    __nv_bfloat16 h1 = __float2bfloat16_rn(f1);
    float r0 = f0 - __bfloat162float(h0);
    float r1 = f1 - __bfloat162float(h1);
    __nv_bfloat16 l0 = __float2bfloat16_rn(r0);
    __nv_bfloat16 l1 = __float2bfloat16_rn(r1);
    hi = (uint32_t)__bfloat16_as_ushort(h0) | ((uint32_t)__bfloat16_as_ushort(h1) << 16);
    lo = (uint32_t)__bfloat16_as_ushort(l0) | ((uint32_t)__bfloat16_as_ushort(l1) << 16);
}

// ---------------- fp32 -> bf16 hi/lo split of all 4 weights ---------------
__global__ void cvt4(const float4* __restrict__ Wq, const float4* __restrict__ Wk,
                     const float4* __restrict__ Wv, const float4* __restrict__ Wo, int n4)
{
    int i = blockIdx.x * 256 + threadIdx.x;
    if (i >= n4) return;
    int z = blockIdx.y;
    const float4* src = (z == 0) ? Wq : (z == 1) ? Wk : (z == 2) ? Wv : Wo;
    float4 v = src[i];
    uint32_t h0, l0, h1, l1;
    split2(v.x, v.y, h0, l0);
    split2(v.z, v.w, h1, l1);
    ((uint2*)g_whi4)[(size_t)z * n4 + i] = make_uint2(h0, h1);
    ((uint2*)g_wlo4)[(size_t)z * n4 + i] = make_uint2(l0, l1);
}

// ======================= HMMA split-bf16 GEMM ==============================
#define TPITCH 144
#define TILE_B 18432
#define STG_B  (4*TILE_B)
#define SM_STG 4096
#define GSMEM  (SM_STG + 3*STG_B)

#define G_LOAD(c, st) do { \
    uint32_t _s = sbase + SM_STG + (st) * STG_B; \
    _Pragma("unroll") \
    for (int _j = 0; _j < 4; _j++) { \
        size_t _g = ((size_t)lrow[_j] * 1024 + (size_t)(c) * 64 + lcg[_j] * 8) * 2; \
        uint32_t _d = _s + lrow[_j] * TPITCH + lcg[_j] * 16; \
        CP16(_d + 0*TILE_B, gb0 + _g); \
        CP16(_d + 1*TILE_B, gb1 + _g); \
        CP16(_d + 2*TILE_B, gb2 + _g); \
        CP16(_d + 3*TILE_B, gb3 + _g); \
    } \
    CP_COMMIT(); \
} while(0)

#define GEMM_BODY(Ahi_, Alo_, Bhi_, Blo_, low_, Bm_, ...) \
    extern __shared__ char smem[]; \
    uint32_t sbase = smem_u32(smem); \
    int tid = threadIdx.x, lane = tid & 31, wid = tid >> 5; \
    int wm = wid >> 1, wn = wid & 1; \
    int m0 = blockIdx.y * 128, n0 = blockIdx.x * 128; \
    ((float4*)smem)[tid] = ((const float4*)((Bm_) + (size_t)n0 * 8))[tid]; \
    const char* gb0 = (const char*)((Ahi_) + (size_t)m0 * DIMN); \
    const char* gb1 = (const char*)((Alo_) + (size_t)m0 * DIMN); \
    const char* gb2 = (const char*)((Bhi_) + (size_t)n0 * DIMN); \
    const char* gb3 = (const char*)((Blo_) + (size_t)n0 * DIMN); \
    int lrow[4], lcg[4]; \
    _Pragma("unroll") \
    for (int j = 0; j < 4; j++) { int L = tid + j * 256; lrow[j] = L >> 3; lcg[j] = L & 7; } \
    G_LOAD(0, 0); G_LOAD(1, 1); G_LOAD(2, 2); \
    float acc[2][8][4]; \
    _Pragma("unroll") \
    for (int a = 0; a < 2; a++) \
        _Pragma("unroll") \
        for (int b = 0; b < 8; b++) \
            _Pragma("unroll") \
            for (int q = 0; q < 4; q++) acc[a][b][q] = 0.f; \
    int arow = lane & 15, akb = (lane >> 4) * 16; \
    int brow = ((lane >> 4) << 3) + (lane & 7), bkb = ((lane >> 3) & 1) * 16; \
    for (int c = 0; c < 16; c++) { \
        int st = c % 3; \
        if (c <= 13) CP_WAIT(2); else if (c == 14) CP_WAIT(1); else CP_WAIT(0); \
        __syncthreads(); \
        uint32_t sA = sbase + SM_STG + st * STG_B; \
        uint32_t sB = sA + 2 * TILE_B; \
        _Pragma("unroll") \
        for (int ks = 0; ks < 4; ks++) { \
            uint32_t ah[2][4], al[2][4]; \
            _Pragma("unroll") \
            for (int mt = 0; mt < 2; mt++) { \
                uint32_t ad = sA + (wm * 32 + mt * 16 + arow) * TPITCH + ks * 32 + akb; \
                ldsm4(ah[mt], ad); \
                ldsm4(al[mt], ad + TILE_B); \
            } \
            uint32_t bh[16], bl[16]; \
            _Pragma("unroll") \
            for (int p = 0; p < 4; p++) { \
                uint32_t bd = sB + (wn * 64 + p * 16 + brow) * TPITCH + ks * 32 + bkb; \
                ldsm4(&bh[4 * p], bd); \
                ldsm4(&bl[4 * p], bd + TILE_B); \
            } \
            _Pragma("unroll") \
            for (int mt = 0; mt < 2; mt++) \
                _Pragma("unroll") \
                for (int nt = 0; nt < 8; nt++) { \
                    int f = (nt >> 1) * 4 + (nt & 1) * 2; \
                    mma_bf16(acc[mt][nt], ah[mt], bh[f], bh[f + 1]); \
                    mma_bf16(acc[mt][nt], ah[mt], bl[f], bl[f + 1]); \
                    mma_bf16(acc[mt][nt], al[mt], bh[f], bh[f + 1]); \
                } \
        } \
        __syncthreads(); \
        if (c + 3 < 16) G_LOAD(c + 3, st); \
    } \
    const float* bms = (const float*)smem; \
    _Pragma("unroll") \
    for (int mt = 0; mt < 2; mt++) { \
        int r0l = wm * 32 + mt * 16 + (lane >> 2); \
        const float* lp0 = (low_) + (size_t)(m0 + r0l) * RR; \
        const float* lp1 = lp0 + 8 * RR; \
        float la0[8], la1[8]; \
        *(float4*)(la0)     = *(const float4*)(lp0); \
        *(float4*)(la0 + 4) = *(const float4*)(lp0 + 4); \
        *(float4*)(la1)     = *(const float4*)(lp1); \
        *(float4*)(la1 + 4) = *(const float4*)(lp1 + 4); \
        _Pragma("unroll") \
        for (int nt = 0; nt < 8; nt++) { \
            int cl = wn * 64 + nt * 8 + (lane & 3) * 2; \
            const float* bp0 = bms + cl * 8; \
            const float* bp1 = bp0 + 8; \
            float a00 = 0, a01 = 0, a10 = 0, a11 = 0; \
            _Pragma("unroll") \
            for (int r = 0; r < 8; r++) { \
                a00 += la0[r] * bp0[r]; a01 += la0[r] * bp1[r]; \
                a10 += la1[r] * bp0[r]; a11 += la1[r] * bp1[r]; \
            } \
            float v00 = acc[mt][nt][0] + a00, v01 = acc[mt][nt][1] + a01; \
            float v10 = acc[mt][nt][2] + a10, v11 = acc[mt][nt][3] + a11; \
            size_t i0 = (size_t)(m0 + r0l) * DIMN + n0 + cl; \
            size_t i1 = i0 + (size_t)8 * DIMN; \
            __VA_ARGS__ \
        } \
    }

// fused q/k/v projections: grid (8, 32, 3)
__global__ __launch_bounds__(256, 1)
void gemm_qkv(const float* __restrict__ Bq, const float* __restrict__ Bk,
              const float* __restrict__ Bv)
{
    int z = blockIdx.z;
    const __nv_bfloat16* Whi = g_whi4 + (size_t)z * DIMN * INNER;
    const __nv_bfloat16* Wlo = g_wlo4 + (size_t)z * DIMN * INNER;
    const float* lowp = g_low + (size_t)z * NT * RR;
    const float* Bmp  = (z == 0) ? Bq : (z == 1) ? Bk : Bv;
    __nv_bfloat16* Chi = (z == 0) ? g_qhi : (z == 1) ? g_khi : g_vhi;
    __nv_bfloat16* Clo = (z == 0) ? g_qlo : (z == 1) ? g_klo : g_vlo;
    GEMM_BODY(g_xhi, g_xlo, Whi, Wlo, lowp, Bmp,
        {
            uint32_t h_;
            uint32_t l_;
            split2(v00, v01, h_, l_);
            *(uint32_t*)(Chi + i0) = h_;
            *(uint32_t*)(Clo + i0) = l_;
            split2(v10, v11, h_, l_);
            *(uint32_t*)(Chi + i1) = h_;
            *(uint32_t*)(Clo + i1) = l_;
        })
}

// output projection: fp32 result to d_out
__global__ __launch_bounds__(256, 1)
void gemm_o(const float* __restrict__ Bo, float* __restrict__ Cf)
{
    const __nv_bfloat16* Whi = g_whi4 + (size_t)3 * DIMN * INNER;
    const __nv_bfloat16* Wlo = g_wlo4 + (size_t)3 * DIMN * INNER;
    GEMM_BODY(g_aohi, g_aolo, Whi, Wlo, g_lowo, Bo,
        {
            *(float2*)(Cf + i0) = make_float2(v00, v01);
            *(float2*)(Cf + i1) = make_float2(v10, v11);
        })
}

// ======================= HMMA flash attention ==============================
#define AST_B 36864
#define ASMEM (2*AST_B)

__global__ __launch_bounds__(128)
void attn_mma()
{
    extern __shared__ char smem[];
    uint32_t sbase = smem_u32(smem);
    int tid = threadIdx.x, lane = tid & 31, wid = tid >> 5;
    int qt = (int)gridDim.x - 1 - (int)blockIdx.x;   // heaviest tiles first
    int h = blockIdx.y, b = blockIdx.z;
    int q0 = qt * 64;
    int nkv = ((qt >> 2) + 1) * 4;

    #pragma unroll
    for (int j = 0; j < 8; j++) {
        int L = tid + j * 128;
        int t = L >> 9, rr = (L >> 3) & 63, cg = L & 7;
        const __nv_bfloat16* src = (t ? g_qlo : g_qhi)
            + ((size_t)(b * TT + q0 + rr) * INNER + h * 64 + cg * 8);
        CP16(sbase + t * 9216 + rr * TPITCH + cg * 16, src);
    }
    CP_COMMIT(); CP_WAIT(0);
    __syncthreads();
    uint32_t qh[4][4], ql[4][4];
    {
        int arow = lane & 15, akb = (lane >> 4) * 16;
        #pragma unroll
        for (int ks = 0; ks < 4; ks++) {
            uint32_t ad = sbase + (wid * 16 + arow) * TPITCH + ks * 32 + akb;
            ldsm4(qh[ks], ad);
            ldsm4(ql[ks], ad + 9216);
        }
    }
    __syncthreads();

#define KV_LOAD(kb, s) do { \
    _Pragma("unroll") \
    for (int _j = 0; _j < 16; _j++) { \
        int _L = tid + _j * 128; \
        int _t = _L >> 9, _rr = (_L >> 3) & 63, _cg = _L & 7; \
        const __nv_bfloat16* _src = \
            (_t == 0 ? g_khi : _t == 1 ? g_klo : _t == 2 ? g_vhi : g_vlo) \
            + ((size_t)(b * TT + (kb) * 64 + _rr) * INNER + h * 64 + _cg * 8); \
        CP16(sbase + (s) * AST_B + _t * 9216 + _rr * TPITCH + _cg * 16, _src); \
    } \
    CP_COMMIT(); \
} while(0)

    KV_LOAD(0, 0); KV_LOAD(1, 1);

    float oacc[8][4];
    #pragma unroll
    for (int d = 0; d < 8; d++)
        #pragma unroll
        for (int q = 0; q < 4; q++) oacc[d][q] = 0.f;
    float mi0 = -1e30f, mi1 = -1e30f, li0 = 0.f, li1 = 0.f;

    int brow = ((lane >> 4) << 3) + (lane & 7), bkb = ((lane >> 3) & 1) * 16;
    int vrow_b = ((lane >> 3) & 1) * 8 + (lane & 7);
    int vcb = ((lane >> 4) << 3) * 2;

    for (int kb = 0; kb < nkv; kb++) {
        if (kb < nkv - 1) { CP_WAIT(1); } else { CP_WAIT(0); }
        __syncthreads();
        int s = kb & 1;
        uint32_t sK = sbase + s * AST_B;
        uint32_t sV = sK + 18432;

        float sacc[8][4];
        #pragma unroll
        for (int nt = 0; nt < 8; nt++)
            #pragma unroll
            for (int q = 0; q < 4; q++) sacc[nt][q] = 0.f;

        #pragma unroll
        for (int ks = 0; ks < 4; ks++) {
            uint32_t kh[16], kl[16];
            #pragma unroll
            for (int p = 0; p < 4; p++) {
                uint32_t bd = sK + (p * 16 + brow) * TPITCH + ks * 32 + bkb;
                ldsm4(&kh[4 * p], bd);
                ldsm4(&kl[4 * p], bd + 9216);
            }
            #pragma unroll
            for (int nt = 0; nt < 8; nt++) {
                int f = (nt >> 1) * 4 + (nt & 1) * 2;
                mma_bf16(sacc[nt], qh[ks], kh[f], kh[f + 1]);
                mma_bf16(sacc[nt], qh[ks], kl[f], kl[f + 1]);
                mma_bf16(sacc[nt], ql[ks], kh[f], kh[f + 1]);
            }
        }
        float mx0 = -1e30f, mx1 = -1e30f;
        #pragma unroll
        for (int nt = 0; nt < 8; nt++) {
            sacc[nt][0] *= 0.125f; sacc[nt][1] *= 0.125f;
            sacc[nt][2] *= 0.125f; sacc[nt][3] *= 0.125f;
            mx0 = fmaxf(mx0, fmaxf(sacc[nt][0], sacc[nt][1]));
            mx1 = fmaxf(mx1, fmaxf(sacc[nt][2], sacc[nt][3]));
        }
        mx0 = fmaxf(mx0, __shfl_xor_sync(~0u, mx0, 1));
        mx0 = fmaxf(mx0, __shfl_xor_sync(~0u, mx0, 2));
        mx1 = fmaxf(mx1, __shfl_xor_sync(~0u, mx1, 1));
        mx1 = fmaxf(mx1, __shfl_xor_sync(~0u, mx1, 2));
        float mn0 = fmaxf(mi0, mx0), mn1 = fmaxf(mi1, mx1);
        float al0 = __expf(mi0 - mn0), al1 = __expf(mi1 - mn1);
        float rs0 = 0.f, rs1 = 0.f;
        #pragma unroll
        for (int nt = 0; nt < 8; nt++) {
            sacc[nt][0] = __expf(sacc[nt][0] - mn0);
            sacc[nt][1] = __expf(sacc[nt][1] - mn0);
            sacc[nt][2] = __expf(sacc[nt][2] - mn1);
            sacc[nt][3] = __expf(sacc[nt][3] - mn1);
            rs0 += sacc[nt][0] + sacc[nt][1];
            rs1 += sacc[nt][2] + sacc[nt][3];
        }
        rs0 += __shfl_xor_sync(~0u, rs0, 1);
        rs0 += __shfl_xor_sync(~0u, rs0, 2);
        rs1 += __shfl_xor_sync(~0u, rs1, 1);
        rs1 += __shfl_xor_sync(~0u, rs1, 2);
        li0 = li0 * al0 + rs0; li1 = li1 * al1 + rs1;
        mi0 = mn0; mi1 = mn1;
        #pragma unroll
        for (int d = 0; d < 8; d++) {
            oacc[d][0] *= al0; oacc[d][1] *= al0;
            oacc[d][2] *= al1; oacc[d][3] *= al1;
        }
        #pragma unroll
        for (int j = 0; j < 4; j++) {
            uint32_t ph[4], pl[4];
            split2(sacc[2*j][0],   sacc[2*j][1],   ph[0], pl[0]);
            split2(sacc[2*j][2],   sacc[2*j][3],   ph[1], pl[1]);
            split2(sacc[2*j+1][0], sacc[2*j+1][1], ph[2], pl[2]);
            split2(sacc[2*j+1][2], sacc[2*j+1][3], ph[3], pl[3]);
            uint32_t vh[16], vl[16];
            #pragma unroll
            for (int p = 0; p < 4; p++) {
                uint32_t vd = sV + (16 * j + vrow_b) * TPITCH + p * 32 + vcb;
                ldsm4t(&vh[4 * p], vd);
                ldsm4t(&vl[4 * p], vd + 9216);
            }
            #pragma unroll
            for (int dt = 0; dt < 8; dt++) {
                int f = (dt >> 1) * 4 + (dt & 1) * 2;
                mma_bf16(oacc[dt], ph, vh[f], vh[f + 1]);
                mma_bf16(oacc[dt], ph, vl[f], vl[f + 1]);
                mma_bf16(oacc[dt], pl, vh[f], vh[f + 1]);
            }
        }
        __syncthreads();
        if (kb + 2 < nkv) KV_LOAD(kb + 2, s);
    }

    int r0l = wid * 16 + (lane >> 2);
    size_t row0 = (size_t)(b * TT + q0 + r0l);
    size_t row1 = row0 + 8;
    float inv0 = 1.f / li0, inv1 = 1.f / li1;
    #pragma unroll
    for (int dt = 0; dt < 8; dt++) {
        int d = h * 64 + dt * 8 + (lane & 3) * 2;
        float v00 = oacc[dt][0] * inv0, v01 = oacc[dt][1] * inv0;
        float v10 = oacc[dt][2] * inv1, v11 = oacc[dt][3] * inv1;
        *(float2*)(g_ao + row0 * INNER + d) = make_float2(v00, v01);
        *(float2*)(g_ao + row1 * INNER + d) = make_float2(v10, v11);
        uint32_t hh, ll;
        split2(v00, v01, hh, ll);
        *(uint32_t*)(g_aohi + row0 * INNER + d) = hh;
        *(uint32_t*)(g_aolo + row0 * INNER + d) = ll;
        split2(v10, v11, hh, ll);
        *(uint32_t*)(g_aohi + row1 * INNER + d) = hh;
        *(uint32_t*)(g_aolo + row1 * INNER + d) = ll;
    }
}

// ---------------- LayerNorm (+ x hi/lo split) ------------------------------
__global__ void ln_kernel(const float* __restrict__ x, const float* __restrict__ mt,
                          const float* __restrict__ gx, const float* __restrict__ bx,
                          const float* __restrict__ gm, const float* __restrict__ bm)
{
    int t = blockIdx.x;
    int which = blockIdx.y;
    const float* src = (which ? mt : x) + (size_t)t * DIMN;
    float*       dst = (which ? g_mn : g_xn) + (size_t)t * DIMN;
    const float* g = which ? gm : gx;
    const float* b = which ? bm : bx;
    int tid = threadIdx.x;
    float4 v = ((const float4*)src)[tid];
    float s  = v.x + v.y + v.z + v.w;
    float sq = v.x*v.x + v.y*v.y + v.z*v.z + v.w*v.w;
    __shared__ float red[2][8];
    #pragma unroll
    for (int m = 16; m; m >>= 1) {
        s  += __shfl_xor_sync(~0u, s, m);
        sq += __shfl_xor_sync(~0u, sq, m);
    }
    int w = tid >> 5, l = tid & 31;
    if (l == 0) { red[0][w] = s; red[1][w] = sq; }
    __syncthreads();
    if (w == 0) {
        float s2 = (l < 8) ? red[0][l] : 0.f;
        float q2 = (l < 8) ? red[1][l] : 0.f;
        #pragma unroll
        for (int m = 4; m; m >>= 1) {
            s2 += __shfl_xor_sync(~0u, s2, m);
            q2 += __shfl_xor_sync(~0u, q2, m);
        }
        if (l == 0) { red[0][0] = s2; red[1][0] = q2; }
    }
    __syncthreads();
    s = red[0][0]; sq = red[1][0];
    float mean = s * (1.f / DIMN);
    float var  = sq * (1.f / DIMN) - mean * mean;
    float rstd = rsqrtf(var + EPS_LN);
    float4 gv = ((const float4*)g)[tid];
    float4 bv = ((const float4*)b)[tid];
    float4 o;
    o.x = (v.x - mean) * rstd * gv.x + bv.x;
    o.y = (v.y - mean) * rstd * gv.y + bv.y;
    o.z = (v.z - mean) * rstd * gv.z + bv.z;
    o.w = (v.w - mean) * rstd * gv.w + bv.w;
    ((float4*)dst)[tid] = o;
    if (which == 0) {
        uint32_t h0, l0, h1, l1;
        split2(o.x, o.y, h0, l0);
        split2(o.z, o.w, h1, l1);
        ((uint2*)(g_xhi + (size_t)t * DIMN))[tid] = make_uint2(h0, h1);
        ((uint2*)(g_xlo + (size_t)t * DIMN))[tid] = make_uint2(l0, l1);
    }
}

// ---------------- per-token rank-8 dots, smem-staged weights ---------------
#define DSMEM (56*256*4)
__global__ __launch_bounds__(512)
void dots2(const float* __restrict__ Gq, const float* __restrict__ Gk,
           const float* __restrict__ Gv, const float* __restrict__ Go,
           const float* __restrict__ Aq, const float* __restrict__ Ak,
           const float* __restrict__ Av)
{
    extern __shared__ float ws[];            // [56][256]
    int tid = threadIdx.x, lane = tid & 31, w = tid >> 5;
    int tok = blockIdx.x * 16 + w;
    const float* wp[7] = {Gq, Gk, Gv, Go, Aq, Ak, Av};

    float acc[56];
    #pragma unroll
    for (int o = 0; o < 56; o++) acc[o] = 0.f;

    for (int c = 0; c < 4; c++) {
        __syncthreads();
        #pragma unroll
        for (int j = 0; j < 7; j++) {
            int idx = tid + j * 512;          // 3584 float4 total
            int o = idx >> 6, k4 = idx & 63;
            *(float4*)&ws[o * 256 + k4 * 4] =
                *(const float4*)(wp[o >> 3] + (size_t)(o & 7) * DIMN + c * 256 + k4 * 4);
        }
        __syncthreads();
        float xc[8], mc[8];
        const float* xb = g_xn + (size_t)tok * DIMN + c * 256 + lane * 8;
        const float* mb = g_mn + (size_t)tok * DIMN + c * 256 + lane * 8;
        *(float4*)(xc)     = *(const float4*)(xb);
        *(float4*)(xc + 4) = *(const float4*)(xb + 4);
        *(float4*)(mc)     = *(const float4*)(mb);
        *(float4*)(mc + 4) = *(const float4*)(mb + 4);
        #pragma unroll
        for (int o = 0; o < 56; o++) {
            const float* s = (o < 32) ? mc : xc;
            const float* wv = &ws[o * 256 + lane * 8];
            float4 w0 = *(const float4*)(wv);
            float4 w1 = *(const float4*)(wv + 4);
            acc[o] += s[0]*w0.x + s[1]*w0.y + s[2]*w0.z + s[3]*w0.w
                    + s[4]*w1.x + s[5]*w1.y + s[6]*w1.z + s[7]*w1.w;
        }
    }
    #pragma unroll
    for (int m = 16; m; m >>= 1)
        #pragma unroll
        for (int o = 0; o < 56; o++) acc[o] += __shfl_xor_sync(~0u, acc[o], m);

    if (lane < 8) {
        int r = lane;
        g_gateo[(size_t)tok * RR + r] = acc[24 + r];
        #pragma unroll
        for (int p = 0; p < 3; p++)
            g_low[((size_t)p * NT + tok) * RR + r] = acc[32 + p * 8 + r] * acc[p * 8 + r] * LORA_SCALE;
    }
}

// ---------------- rank-8 o-dots, smem-staged Ao ----------------------------
__global__ __launch_bounds__(512)
void lowo2(const float* __restrict__ Ao)
{
    __shared__ float ws[8 * 256];
    int tid = threadIdx.x, lane = tid & 31, w = tid >> 5;
    int tok = blockIdx.x * 16 + w;
    float acc[8] = {0, 0, 0, 0, 0, 0, 0, 0};
    for (int c = 0; c < 4; c++) {
        __syncthreads();
        {
            int o = tid >> 6, k4 = tid & 63;   // 512 float4 = 1/thread
            *(float4*)&ws[o * 256 + k4 * 4] =
                *(const float4*)(Ao + (size_t)o * INNER + c * 256 + k4 * 4);
        }
        __syncthreads();
        float ac[8];
        const float* ab = g_ao + (size_t)tok * INNER + c * 256 + lane * 8;
        *(float4*)(ac)     = *(const float4*)(ab);
        *(float4*)(ac + 4) = *(const float4*)(ab + 4);
        #pragma unroll
        for (int o = 0; o < 8; o++) {
            const float* wv = &ws[o * 256 + lane * 8];
            float4 w0 = *(const float4*)(wv);
            float4 w1 = *(const float4*)(wv + 4);
            acc[o] += ac[0]*w0.x + ac[1]*w0.y + ac[2]*w0.z + ac[3]*w0.w
                    + ac[4]*w1.x + ac[5]*w1.y + ac[6]*w1.z + ac[7]*w1.w;
        }
    }
    #pragma unroll
    for (int m = 16; m; m >>= 1)
        #pragma unroll
        for (int o = 0; o < 8; o++) acc[o] += __shfl_xor_sync(~0u, acc[o], m);
    if (lane < 8)
        g_lowo[(size_t)tok * RR + lane] = acc[lane] * g_gateo[(size_t)tok * RR + lane] * LORA_SCALE;
}

// ---------------- launch ---------------------------------------------------
extern "C" void kernel_launch(void* const* d_in, const int* in_sizes, int n_in,
                              void* d_out, int out_size)
{
    const float* x  = (const float*)d_in[0];
    const float* mt = (const float*)d_in[1];
    const float* ng = (const float*)d_in[2];
    const float* nb = (const float*)d_in[3];
    const float* mg = (const float*)d_in[4];
    const float* mb = (const float*)d_in[5];
    const float* Wq = (const float*)d_in[6];
    const float* Aq = (const float*)d_in[7];
    const float* Bq = (const float*)d_in[8];
    const float* Gq = (const float*)d_in[9];
    const float* Wk = (const float*)d_in[10];
    const float* Ak = (const float*)d_in[11];
    const float* Bk = (const float*)d_in[12];
    const float* Gk = (const float*)d_in[13];
    const float* Wv = (const float*)d_in[14];
    const float* Av = (const float*)d_in[15];
    const float* Bv = (const float*)d_in[16];
    const float* Gv = (const float*)d_in[17];
    const float* Wo = (const float*)d_in[18];
    const float* Ao = (const float*)d_in[19];
    const float* Bo = (const float*)d_in[20];
    const float* Go = (const float*)d_in[21];
    float* out = (float*)d_out;

    cudaFuncSetAttribute(gemm_qkv, cudaFuncAttributeMaxDynamicSharedMemorySize, GSMEM);
    cudaFuncSetAttribute(gemm_o,   cudaFuncAttributeMaxDynamicSharedMemorySize, GSMEM);
    cudaFuncSetAttribute(attn_mma, cudaFuncAttributeMaxDynamicSharedMemorySize, ASMEM);
    cudaFuncSetAttribute(dots2,    cudaFuncAttributeMaxDynamicSharedMemorySize, DSMEM);

    const int n4w = DIMN * INNER / 4;

    cvt4<<<dim3((n4w + 255) / 256, 4), 256>>>((const float4*)Wq, (const float4*)Wk,
                                              (const float4*)Wv, (const float4*)Wo, n4w);
    ln_kernel<<<dim3(NT, 2), 256>>>(x, mt, ng, nb, mg, mb);
    dots2<<<NT / 16, 512, DSMEM>>>(Gq, Gk, Gv, Go, Aq, Ak, Av);

    gemm_qkv<<<dim3(8, 32, 3), 256, GSMEM>>>(Bq, Bk, Bv);

    attn_mma<<<dim3(32, HEADS, BB), 128, ASMEM>>>();
    lowo2<<<NT / 16, 512>>>(Ao);

    gemm_o<<<dim3(8, 32), 256, GSMEM>>>(Bo, out);
}

// round 13
// speedup vs baseline: 1.3394x; 1.3394x over previous
#include <cuda_runtime.h>
#include <cuda_fp16.h>
#include <cstdint>
#include <math.h>

#define BB 2
#define TT 2048
#define DIMN 1024
#define HEADS 16
#define DH 64
#define INNER 1024
#define RR 8
#define NT (BB*TT)
#define LORA_SCALE 0.25f
#define EPS_LN 1e-5f

// ---------------- static scratch -------------------------------------------
__device__ float g_xn[NT*DIMN];
__device__ float g_mn[NT*DIMN];
__device__ float g_ao[NT*INNER];
__device__ float g_low[3*NT*RR];
__device__ float g_gateo[NT*RR];
__device__ float g_lowo[NT*RR];
__device__ __half g_xh [NT*DIMN];
__device__ __half g_whi4[4*DIMN*INNER];
__device__ __half g_wlo4[4*DIMN*INNER];
__device__ __half g_qh [NT*INNER];
__device__ __half g_kh [NT*INNER];
__device__ __half g_kl [NT*INNER];
__device__ __half g_vh [NT*INNER];
__device__ __half g_vl [NT*INNER];
__device__ __half g_aoh[NT*INNER];

// ---------------- helpers --------------------------------------------------
__device__ __forceinline__ uint32_t smem_u32(const void* p){
    uint32_t a;
    asm("{ .reg .u64 t; cvta.to.shared.u64 t, %1; cvt.u32.u64 %0, t; }" : "=r"(a) : "l"(p));
    return a;
}
#define CP16(sm, g) asm volatile("cp.async.cg.shared.global [%0], [%1], 16;" :: "r"(sm), "l"(g) : "memory")
#define CP_COMMIT() asm volatile("cp.async.commit_group;" ::: "memory")
#define CP_WAIT(n)  asm volatile("cp.async.wait_group %0;" :: "n"(n) : "memory")

__device__ __forceinline__ void ldsm4(uint32_t* r, uint32_t a){
    asm volatile("ldmatrix.sync.aligned.m8n8.x4.shared.b16 {%0,%1,%2,%3}, [%4];"
        : "=r"(r[0]),"=r"(r[1]),"=r"(r[2]),"=r"(r[3]) : "r"(a));
}
__device__ __forceinline__ void ldsm4t(uint32_t* r, uint32_t a){
    asm volatile("ldmatrix.sync.aligned.m8n8.x4.trans.shared.b16 {%0,%1,%2,%3}, [%4];"
        : "=r"(r[0]),"=r"(r[1]),"=r"(r[2]),"=r"(r[3]) : "r"(a));
}
__device__ __forceinline__ void mma_f16(float* c, const uint32_t* a, uint32_t b0, uint32_t b1){
    asm volatile("mma.sync.aligned.m16n8k16.row.col.f32.f16.f16.f32 "
        "{%0,%1,%2,%3}, {%4,%5,%6,%7}, {%8,%9}, {%0,%1,%2,%3};"
        : "+f"(c[0]),"+f"(c[1]),"+f"(c[2]),"+f"(c[3])
        : "r"(a[0]),"r"(a[1]),"r"(a[2]),"r"(a[3]),"r"(b0),"r"(b1));
}
__device__ __forceinline__ uint32_t packh(float f0, float f1){
    __half h0 = __float2half_rn(f0), h1 = __float2half_rn(f1);
    return (uint32_t)__half_as_ushort(h0) | ((uint32_t)__half_as_ushort(h1) << 16);
}
__device__ __forceinline__ void splith2(float f0, float f1, uint32_t& hi, uint32_t& lo){
    __half h0 = __float2half_rn(f0), h1 = __float2half_rn(f1);
    float r0 = f0 - __half2float(h0), r1 = f1 - __half2float(h1);
    hi = (uint32_t)__half_as_ushort(h0) | ((uint32_t)__half_as_ushort(h1) << 16);
    lo = (uint32_t)__half_as_ushort(__float2half_rn(r0))
       | ((uint32_t)__half_as_ushort(__float2half_rn(r1)) << 16);
}

// ---------------- fp32 -> fp16 hi/lo split of all 4 weights ----------------
__global__ void cvt4(const float4* __restrict__ Wq, const float4* __restrict__ Wk,
                     const float4* __restrict__ Wv, const float4* __restrict__ Wo, int n4)
{
    int i = blockIdx.x * 256 + threadIdx.x;
    if (i >= n4) return;
    int z = blockIdx.y;
    const float4* src = (z == 0) ? Wq : (z == 1) ? Wk : (z == 2) ? Wv : Wo;
    float4 v = src[i];
    uint32_t h0, l0, h1, l1;
    splith2(v.x, v.y, h0, l0);
    splith2(v.z, v.w, h1, l1);
    ((uint2*)g_whi4)[(size_t)z * n4 + i] = make_uint2(h0, h1);
    ((uint2*)g_wlo4)[(size_t)z * n4 + i] = make_uint2(l0, l1);
}

// ======================= HMMA fp16 2-term GEMM =============================
// C[4096, out] = A@(Wh+Wl)^T + low@Bm^T.  BM=128, BN=64, K-chunk=64, 3 stages.
// A fp16 hi only. 8 warps as 4x2, warp tile 32x32. 2 CTAs/SM.
#define TPITCH 144
#define ATILE_B 18432          /* 128*144 */
#define BTILE_B 9216           /* 64*144 */
#define STG_B   36864          /* A + Bhi + Blo */
#define SM_STG  2048
#define GSMEM   (SM_STG + 3*STG_B)   /* 112640 */

#define G_LOAD(c, st) do { \
    uint32_t _s = sbase + SM_STG + (st) * STG_B; \
    _Pragma("unroll") \
    for (int _j = 0; _j < 4; _j++) { \
        int _r = (tid >> 3) + _j * 32; \
        CP16(_s + _r * TPITCH + cg16, gA + (size_t)_r * 2048 + (c) * 128 + cg16); \
    } \
    _Pragma("unroll") \
    for (int _j = 0; _j < 2; _j++) { \
        int _r = (tid >> 3) + _j * 32; \
        size_t _g = (size_t)_r * 2048 + (c) * 128 + cg16; \
        CP16(_s + ATILE_B + _r * TPITCH + cg16, gBh + _g); \
        CP16(_s + ATILE_B + BTILE_B + _r * TPITCH + cg16, gBl + _g); \
    } \
    CP_COMMIT(); \
} while(0)

#define GEMM_BODY(Ah_, Bhi_, Blo_, low_, Bm_, ...) \
    extern __shared__ char smem[]; \
    uint32_t sbase = smem_u32(smem); \
    int tid = threadIdx.x, lane = tid & 31, wid = tid >> 5; \
    int wm = wid >> 1, wn = wid & 1; \
    int m0 = blockIdx.y * 128, n0 = blockIdx.x * 64; \
    if (tid < 128) ((float4*)smem)[tid] = ((const float4*)((Bm_) + (size_t)n0 * 8))[tid]; \
    const char* gA  = (const char*)((Ah_)  + (size_t)m0 * DIMN); \
    const char* gBh = (const char*)((Bhi_) + (size_t)n0 * DIMN); \
    const char* gBl = (const char*)((Blo_) + (size_t)n0 * DIMN); \
    int cg16 = (tid & 7) * 16; \
    G_LOAD(0, 0); G_LOAD(1, 1); G_LOAD(2, 2); \
    float acc[2][4][4]; \
    _Pragma("unroll") \
    for (int a = 0; a < 2; a++) \
        _Pragma("unroll") \
        for (int b = 0; b < 4; b++) \
            _Pragma("unroll") \
            for (int q = 0; q < 4; q++) acc[a][b][q] = 0.f; \
    int arow = lane & 15, akb = (lane >> 4) * 16; \
    int browl = ((lane >> 4) << 3) + (lane & 7), bkb = ((lane >> 3) & 1) * 16; \
    for (int c = 0; c < 16; c++) { \
        int st = c % 3; \
        if (c <= 13) CP_WAIT(2); else if (c == 14) CP_WAIT(1); else CP_WAIT(0); \
        __syncthreads(); \
        uint32_t sA = sbase + SM_STG + st * STG_B; \
        uint32_t sBh = sA + ATILE_B, sBl = sBh + BTILE_B; \
        _Pragma("unroll") \
        for (int ks = 0; ks < 4; ks++) { \
            uint32_t ah[2][4]; \
            _Pragma("unroll") \
            for (int mt = 0; mt < 2; mt++) \
                ldsm4(ah[mt], sA + (wm * 32 + mt * 16 + arow) * TPITCH + ks * 32 + akb); \
            uint32_t bh[8], bl[8]; \
            _Pragma("unroll") \
            for (int p = 0; p < 2; p++) { \
                uint32_t off = (wn * 32 + p * 16 + browl) * TPITCH + ks * 32 + bkb; \
                ldsm4(&bh[4 * p], sBh + off); \
                ldsm4(&bl[4 * p], sBl + off); \
            } \
            _Pragma("unroll") \
            for (int mt = 0; mt < 2; mt++) \
                _Pragma("unroll") \
                for (int nt = 0; nt < 4; nt++) { \
                    int f = (nt >> 1) * 4 + (nt & 1) * 2; \
                    mma_f16(acc[mt][nt], ah[mt], bh[f], bh[f + 1]); \
                    mma_f16(acc[mt][nt], ah[mt], bl[f], bl[f + 1]); \
                } \
        } \
        __syncthreads(); \
        if (c + 3 < 16) G_LOAD(c + 3, st); \
    } \
    const float* bms = (const float*)smem; \
    _Pragma("unroll") \
    for (int mt = 0; mt < 2; mt++) { \
        int r0l = wm * 32 + mt * 16 + (lane >> 2); \
        const float* lp0 = (low_) + (size_t)(m0 + r0l) * RR; \
        const float* lp1 = lp0 + 8 * RR; \
        float la0[8], la1[8]; \
        *(float4*)(la0)     = *(const float4*)(lp0); \
        *(float4*)(la0 + 4) = *(const float4*)(lp0 + 4); \
        *(float4*)(la1)     = *(const float4*)(lp1); \
        *(float4*)(la1 + 4) = *(const float4*)(lp1 + 4); \
        _Pragma("unroll") \
        for (int nt = 0; nt < 4; nt++) { \
            int cl = wn * 32 + nt * 8 + (lane & 3) * 2; \
            const float* bp0 = bms + cl * 8; \
            const float* bp1 = bp0 + 8; \
            float a00 = 0, a01 = 0, a10 = 0, a11 = 0; \
            _Pragma("unroll") \
            for (int r = 0; r < 8; r++) { \
                a00 += la0[r] * bp0[r]; a01 += la0[r] * bp1[r]; \
                a10 += la1[r] * bp0[r]; a11 += la1[r] * bp1[r]; \
            } \
            float v00 = acc[mt][nt][0] + a00, v01 = acc[mt][nt][1] + a01; \
            float v10 = acc[mt][nt][2] + a10, v11 = acc[mt][nt][3] + a11; \
            size_t i0 = (size_t)(m0 + r0l) * INNER + n0 + cl; \
            size_t i1 = i0 + (size_t)8 * INNER; \
            __VA_ARGS__ \
        } \
    }

// fused q/k/v projections: grid (16, 32, 3). q: hi only; k/v: hi+lo.
__global__ __launch_bounds__(256, 2)
void gemm_qkv(const float* __restrict__ Bq, const float* __restrict__ Bk,
              const float* __restrict__ Bv)
{
    int z = blockIdx.z;
    const __half* Whi = g_whi4 + (size_t)z * DIMN * INNER;
    const __half* Wlo = g_wlo4 + (size_t)z * DIMN * INNER;
    const float* lowp = g_low + (size_t)z * NT * RR;
    const float* Bmp  = (z == 0) ? Bq : (z == 1) ? Bk : Bv;
    __half* Chi = (z == 0) ? g_qh : (z == 1) ? g_kh : g_vh;
    __half* Clo = (z == 0) ? (__half*)0 : (z == 1) ? g_kl : g_vl;
    GEMM_BODY(g_xh, Whi, Wlo, lowp, Bmp,
        {
            if (Clo) {
                uint32_t h_;
                uint32_t l_;
                splith2(v00, v01, h_, l_);
                *(uint32_t*)(Chi + i0) = h_;
                *(uint32_t*)(Clo + i0) = l_;
                splith2(v10, v11, h_, l_);
                *(uint32_t*)(Chi + i1) = h_;
                *(uint32_t*)(Clo + i1) = l_;
            } else {
                *(uint32_t*)(Chi + i0) = packh(v00, v01);
                *(uint32_t*)(Chi + i1) = packh(v10, v11);
            }
        })
}

// output projection: fp32 result to d_out
__global__ __launch_bounds__(256, 2)
void gemm_o(const float* __restrict__ Bo, float* __restrict__ Cf)
{
    const __half* Whi = g_whi4 + (size_t)3 * DIMN * INNER;
    const __half* Wlo = g_wlo4 + (size_t)3 * DIMN * INNER;
    GEMM_BODY(g_aoh, Whi, Wlo, g_lowo, Bo,
        {
            *(float2*)(Cf + i0) = make_float2(v00, v01);
            *(float2*)(Cf + i1) = make_float2(v10, v11);
        })
}

// ======================= HMMA fp16 2-term flash attention ==================
// BQ=64, BKV=64, 4 warps. Q hi-only in regs; K,V hi+lo staged; P hi-only.
#define AST_B 36864          /* kh, kl, vh, vl tiles of 9216 */
#define ASMEM (2*AST_B)

__global__ __launch_bounds__(128)
void attn_mma()
{
    extern __shared__ char smem[];
    uint32_t sbase = smem_u32(smem);
    int tid = threadIdx.x, lane = tid & 31, wid = tid >> 5;
    int qt = (int)gridDim.x - 1 - (int)blockIdx.x;   // heaviest tiles first
    int h = blockIdx.y, b = blockIdx.z;
    int q0 = qt * 64;
    int nkv = ((qt >> 2) + 1) * 4;

    // stage Q hi (64 x 64 fp16), read A fragments to registers
    #pragma unroll
    for (int j = 0; j < 4; j++) {
        int L = tid + j * 128;
        int rr = L >> 3, cg = L & 7;
        const __half* src = g_qh + ((size_t)(b * TT + q0 + rr) * INNER + h * 64 + cg * 8);
        CP16(sbase + rr * TPITCH + cg * 16, src);
    }
    CP_COMMIT(); CP_WAIT(0);
    __syncthreads();
    uint32_t qh[4][4];
    {
        int arow = lane & 15, akb = (lane >> 4) * 16;
        #pragma unroll
        for (int ks = 0; ks < 4; ks++)
            ldsm4(qh[ks], sbase + (wid * 16 + arow) * TPITCH + ks * 32 + akb);
    }
    __syncthreads();

#define KV_LOAD(kb, s) do { \
    _Pragma("unroll") \
    for (int _j = 0; _j < 16; _j++) { \
        int _L = tid + _j * 128; \
        int _t = _L >> 9, _rr = (_L >> 3) & 63, _cg = _L & 7; \
        const __half* _src = \
            (_t == 0 ? g_kh : _t == 1 ? g_kl : _t == 2 ? g_vh : g_vl) \
            + ((size_t)(b * TT + (kb) * 64 + _rr) * INNER + h * 64 + _cg * 8); \
        CP16(sbase + (s) * AST_B + _t * 9216 + _rr * TPITCH + _cg * 16, _src); \
    } \
    CP_COMMIT(); \
} while(0)

    KV_LOAD(0, 0); KV_LOAD(1, 1);

    float oacc[8][4];
    #pragma unroll
    for (int d = 0; d < 8; d++)
        #pragma unroll
        for (int q = 0; q < 4; q++) oacc[d][q] = 0.f;
    float mi0 = -1e30f, mi1 = -1e30f, li0 = 0.f, li1 = 0.f;

    int browl = ((lane >> 4) << 3) + (lane & 7), bkb = ((lane >> 3) & 1) * 16;
    int vrow_b = ((lane >> 3) & 1) * 8 + (lane & 7);
    int vcb = ((lane >> 4) << 3) * 2;

    for (int kb = 0; kb < nkv; kb++) {
        if (kb < nkv - 1) { CP_WAIT(1); } else { CP_WAIT(0); }
        __syncthreads();
        int s = kb & 1;
        uint32_t sK = sbase + s * AST_B;
        uint32_t sV = sK + 18432;

        float sacc[8][4];
        #pragma unroll
        for (int nt = 0; nt < 8; nt++)
            #pragma unroll
            for (int q = 0; q < 4; q++) sacc[nt][q] = 0.f;

        #pragma unroll
        for (int ks = 0; ks < 4; ks++) {
            uint32_t kh[16], kl[16];
            #pragma unroll
            for (int p = 0; p < 4; p++) {
                uint32_t bd = sK + (p * 16 + browl) * TPITCH + ks * 32 + bkb;
                ldsm4(&kh[4 * p], bd);
                ldsm4(&kl[4 * p], bd + 9216);
            }
            #pragma unroll
            for (int nt = 0; nt < 8; nt++) {
                int f = (nt >> 1) * 4 + (nt & 1) * 2;
                mma_f16(sacc[nt], qh[ks], kh[f], kh[f + 1]);
                mma_f16(sacc[nt], qh[ks], kl[f], kl[f + 1]);
            }
        }
        float mx0 = -1e30f, mx1 = -1e30f;
        #pragma unroll
        for (int nt = 0; nt < 8; nt++) {
            sacc[nt][0] *= 0.125f; sacc[nt][1] *= 0.125f;
            sacc[nt][2] *= 0.125f; sacc[nt][3] *= 0.125f;
            mx0 = fmaxf(mx0, fmaxf(sacc[nt][0], sacc[nt][1]));
            mx1 = fmaxf(mx1, fmaxf(sacc[nt][2], sacc[nt][3]));
        }
        mx0 = fmaxf(mx0, __shfl_xor_sync(~0u, mx0, 1));
        mx0 = fmaxf(mx0, __shfl_xor_sync(~0u, mx0, 2));
        mx1 = fmaxf(mx1, __shfl_xor_sync(~0u, mx1, 1));
        mx1 = fmaxf(mx1, __shfl_xor_sync(~0u, mx1, 2));
        float mn0 = fmaxf(mi0, mx0), mn1 = fmaxf(mi1, mx1);
        float al0 = __expf(mi0 - mn0), al1 = __expf(mi1 - mn1);
        float rs0 = 0.f, rs1 = 0.f;
        #pragma unroll
        for (int nt = 0; nt < 8; nt++) {
            sacc[nt][0] = __expf(sacc[nt][0] - mn0);
            sacc[nt][1] = __expf(sacc[nt][1] - mn0);
            sacc[nt][2] = __expf(sacc[nt][2] - mn1);
            sacc[nt][3] = __expf(sacc[nt][3] - mn1);
            rs0 += sacc[nt][0] + sacc[nt][1];
            rs1 += sacc[nt][2] + sacc[nt][3];
        }
        rs0 += __shfl_xor_sync(~0u, rs0, 1);
        rs0 += __shfl_xor_sync(~0u, rs0, 2);
        rs1 += __shfl_xor_sync(~0u, rs1, 1);
        rs1 += __shfl_xor_sync(~0u, rs1, 2);
        li0 = li0 * al0 + rs0; li1 = li1 * al1 + rs1;
        mi0 = mn0; mi1 = mn1;
        #pragma unroll
        for (int d = 0; d < 8; d++) {
            oacc[d][0] *= al0; oacc[d][1] *= al0;
            oacc[d][2] *= al1; oacc[d][3] *= al1;
        }
        #pragma unroll
        for (int j = 0; j < 4; j++) {
            uint32_t ph[4];
            ph[0] = packh(sacc[2*j][0],   sacc[2*j][1]);
            ph[1] = packh(sacc[2*j][2],   sacc[2*j][3]);
            ph[2] = packh(sacc[2*j+1][0], sacc[2*j+1][1]);
            ph[3] = packh(sacc[2*j+1][2], sacc[2*j+1][3]);
            uint32_t vh[16], vl[16];
            #pragma unroll
            for (int p = 0; p < 4; p++) {
                uint32_t vd = sV + (16 * j + vrow_b) * TPITCH + p * 32 + vcb;
                ldsm4t(&vh[4 * p], vd);
                ldsm4t(&vl[4 * p], vd + 9216);
            }
            #pragma unroll
            for (int dt = 0; dt < 8; dt++) {
                int f = (dt >> 1) * 4 + (dt & 1) * 2;
                mma_f16(oacc[dt], ph, vh[f], vh[f + 1]);
                mma_f16(oacc[dt], ph, vl[f], vl[f + 1]);
            }
        }
        __syncthreads();
        if (kb + 2 < nkv) KV_LOAD(kb + 2, s);
    }

    int r0l = wid * 16 + (lane >> 2);
    size_t row0 = (size_t)(b * TT + q0 + r0l);
    size_t row1 = row0 + 8;
    float inv0 = 1.f / li0, inv1 = 1.f / li1;
    #pragma unroll
    for (int dt = 0; dt < 8; dt++) {
        int d = h * 64 + dt * 8 + (lane & 3) * 2;
        float v00 = oacc[dt][0] * inv0, v01 = oacc[dt][1] * inv0;
        float v10 = oacc[dt][2] * inv1, v11 = oacc[dt][3] * inv1;
        *(float2*)(g_ao + row0 * INNER + d) = make_float2(v00, v01);
        *(float2*)(g_ao + row1 * INNER + d) = make_float2(v10, v11);
        *(uint32_t*)(g_aoh + row0 * INNER + d) = packh(v00, v01);
        *(uint32_t*)(g_aoh + row1 * INNER + d) = packh(v10, v11);
    }
}

// ---------------- LayerNorm (+ x fp16 hi) ----------------------------------
__global__ void ln_kernel(const float* __restrict__ x, const float* __restrict__ mt,
                          const float* __restrict__ gx, const float* __restrict__ bx,
                          const float* __restrict__ gm, const float* __restrict__ bm)
{
    int t = blockIdx.x;
    int which = blockIdx.y;
    const float* src = (which ? mt : x) + (size_t)t * DIMN;
    float*       dst = (which ? g_mn : g_xn) + (size_t)t * DIMN;
    const float* g = which ? gm : gx;
    const float* b = which ? bm : bx;
    int tid = threadIdx.x;
    float4 v = ((const float4*)src)[tid];
    float s  = v.x + v.y + v.z + v.w;
    float sq = v.x*v.x + v.y*v.y + v.z*v.z + v.w*v.w;
    __shared__ float red[2][8];
    #pragma unroll
    for (int m = 16; m; m >>= 1) {
        s  += __shfl_xor_sync(~0u, s, m);
        sq += __shfl_xor_sync(~0u, sq, m);
    }
    int w = tid >> 5, l = tid & 31;
    if (l == 0) { red[0][w] = s; red[1][w] = sq; }
    __syncthreads();
    if (w == 0) {
        float s2 = (l < 8) ? red[0][l] : 0.f;
        float q2 = (l < 8) ? red[1][l] : 0.f;
        #pragma unroll
        for (int m = 4; m; m >>= 1) {
            s2 += __shfl_xor_sync(~0u, s2, m);
            q2 += __shfl_xor_sync(~0u, q2, m);
        }
        if (l == 0) { red[0][0] = s2; red[1][0] = q2; }
    }
    __syncthreads();
    s = red[0][0]; sq = red[1][0];
    float mean = s * (1.f / DIMN);
    float var  = sq * (1.f / DIMN) - mean * mean;
    float rstd = rsqrtf(var + EPS_LN);
    float4 gv = ((const float4*)g)[tid];
    float4 bv = ((const float4*)b)[tid];
    float4 o;
    o.x = (v.x - mean) * rstd * gv.x + bv.x;
    o.y = (v.y - mean) * rstd * gv.y + bv.y;
    o.z = (v.z - mean) * rstd * gv.z + bv.z;
    o.w = (v.w - mean) * rstd * gv.w + bv.w;
    ((float4*)dst)[tid] = o;
    if (which == 0)
        ((uint2*)(g_xh + (size_t)t * DIMN))[tid] =
            make_uint2(packh(o.x, o.y), packh(o.z, o.w));
}

// ---------------- per-token rank-8 dots, smem-staged weights ---------------
#define DSMEM (56*256*4)
__global__ __launch_bounds__(512)
void dots2(const float* __restrict__ Gq, const float* __restrict__ Gk,
           const float* __restrict__ Gv, const float* __restrict__ Go,
           const float* __restrict__ Aq, const float* __restrict__ Ak,
           const float* __restrict__ Av)
{
    extern __shared__ float ws[];            // [56][256]
    int tid = threadIdx.x, lane = tid & 31, w = tid >> 5;
    int tok = blockIdx.x * 16 + w;
    const float* wp[7] = {Gq, Gk, Gv, Go, Aq, Ak, Av};

    float acc[56];
    #pragma unroll
    for (int o = 0; o < 56; o++) acc[o] = 0.f;

    for (int c = 0; c < 4; c++) {
        __syncthreads();
        #pragma unroll
        for (int j = 0; j < 7; j++) {
            int idx = tid + j * 512;
            int o = idx >> 6, k4 = idx & 63;
            *(float4*)&ws[o * 256 + k4 * 4] =
                *(const float4*)(wp[o >> 3] + (size_t)(o & 7) * DIMN + c * 256 + k4 * 4);
        }
        __syncthreads();
        float xc[8], mc[8];
        const float* xb = g_xn + (size_t)tok * DIMN + c * 256 + lane * 8;
        const float* mb = g_mn + (size_t)tok * DIMN + c * 256 + lane * 8;
        *(float4*)(xc)     = *(const float4*)(xb);
        *(float4*)(xc + 4) = *(const float4*)(xb + 4);
        *(float4*)(mc)     = *(const float4*)(mb);
        *(float4*)(mc + 4) = *(const float4*)(mb + 4);
        #pragma unroll
        for (int o = 0; o < 56; o++) {
            const float* s = (o < 32) ? mc : xc;
            const float* wv = &ws[o * 256 + lane * 8];
            float4 w0 = *(const float4*)(wv);
            float4 w1 = *(const float4*)(wv + 4);
            acc[o] += s[0]*w0.x + s[1]*w0.y + s[2]*w0.z + s[3]*w0.w
                    + s[4]*w1.x + s[5]*w1.y + s[6]*w1.z + s[7]*w1.w;
        }
    }
    #pragma unroll
    for (int m = 16; m; m >>= 1)
        #pragma unroll
        for (int o = 0; o < 56; o++) acc[o] += __shfl_xor_sync(~0u, acc[o], m);

    if (lane < 8) {
        int r = lane;
        g_gateo[(size_t)tok * RR + r] = acc[24 + r];
        #pragma unroll
        for (int p = 0; p < 3; p++)
            g_low[((size_t)p * NT + tok) * RR + r] = acc[32 + p * 8 + r] * acc[p * 8 + r] * LORA_SCALE;
    }
}

// ---------------- rank-8 o-dots, smem-staged Ao ----------------------------
__global__ __launch_bounds__(512)
void lowo2(const float* __restrict__ Ao)
{
    __shared__ float ws[8 * 256];
    int tid = threadIdx.x, lane = tid & 31, w = tid >> 5;
    int tok = blockIdx.x * 16 + w;
    float acc[8] = {0, 0, 0, 0, 0, 0, 0, 0};
    for (int c = 0; c < 4; c++) {
        __syncthreads();
        {
            int o = tid >> 6, k4 = tid & 63;
            *(float4*)&ws[o * 256 + k4 * 4] =
                *(const float4*)(Ao + (size_t)o * INNER + c * 256 + k4 * 4);
        }
        __syncthreads();
        float ac[8];
        const float* ab = g_ao + (size_t)tok * INNER + c * 256 + lane * 8;
        *(float4*)(ac)     = *(const float4*)(ab);
        *(float4*)(ac + 4) = *(const float4*)(ab + 4);
        #pragma unroll
        for (int o = 0; o < 8; o++) {
            const float* wv = &ws[o * 256 + lane * 8];
            float4 w0 = *(const float4*)(wv);
            float4 w1 = *(const float4*)(wv + 4);
            acc[o] += ac[0]*w0.x + ac[1]*w0.y + ac[2]*w0.z + ac[3]*w0.w
                    + ac[4]*w1.x + ac[5]*w1.y + ac[6]*w1.z + ac[7]*w1.w;
        }
    }
    #pragma unroll
    for (int m = 16; m; m >>= 1)
        #pragma unroll
        for (int o = 0; o < 8; o++) acc[o] += __shfl_xor_sync(~0u, acc[o], m);
    if (lane < 8)
        g_lowo[(size_t)tok * RR + lane] = acc[lane] * g_gateo[(size_t)tok * RR + lane] * LORA_SCALE;
}

// ---------------- launch ---------------------------------------------------
extern "C" void kernel_launch(void* const* d_in, const int* in_sizes, int n_in,
                              void* d_out, int out_size)
{
    const float* x  = (const float*)d_in[0];
    const float* mt = (const float*)d_in[1];
    const float* ng = (const float*)d_in[2];
    const float* nb = (const float*)d_in[3];
    const float* mg = (const float*)d_in[4];
    const float* mb = (const float*)d_in[5];
    const float* Wq = (const float*)d_in[6];
    const float* Aq = (const float*)d_in[7];
    const float* Bq = (const float*)d_in[8];
    const float* Gq = (const float*)d_in[9];
    const float* Wk = (const float*)d_in[10];
    const float* Ak = (const float*)d_in[11];
    const float* Bk = (const float*)d_in[12];
    const float* Gk = (const float*)d_in[13];
    const float* Wv = (const float*)d_in[14];
    const float* Av = (const float*)d_in[15];
    const float* Bv = (const float*)d_in[16];
    const float* Gv = (const float*)d_in[17];
    const float* Wo = (const float*)d_in[18];
    const float* Ao = (const float*)d_in[19];
    const float* Bo = (const float*)d_in[20];
    const float* Go = (const float*)d_in[21];
    float* out = (float*)d_out;

    cudaFuncSetAttribute(gemm_qkv, cudaFuncAttributeMaxDynamicSharedMemorySize, GSMEM);
    cudaFuncSetAttribute(gemm_o,   cudaFuncAttributeMaxDynamicSharedMemorySize, GSMEM);
    cudaFuncSetAttribute(attn_mma, cudaFuncAttributeMaxDynamicSharedMemorySize, ASMEM);
    cudaFuncSetAttribute(dots2,    cudaFuncAttributeMaxDynamicSharedMemorySize, DSMEM);

    const int n4w = DIMN * INNER / 4;

    cvt4<<<dim3((n4w + 255) / 256, 4), 256>>>((const float4*)Wq, (const float4*)Wk,
                                              (const float4*)Wv, (const float4*)Wo, n4w);
    ln_kernel<<<dim3(NT, 2), 256>>>(x, mt, ng, nb, mg, mb);
    dots2<<<NT / 16, 512, DSMEM>>>(Gq, Gk, Gv, Go, Aq, Ak, Av);

    gemm_qkv<<<dim3(16, 32, 3), 256, GSMEM>>>(Bq, Bk, Bv);

    attn_mma<<<dim3(32, HEADS, BB), 128, ASMEM>>>();
    lowo2<<<NT / 16, 512>>>(Ao);

    gemm_o<<<dim3(16, 32), 256, GSMEM>>>(Bo, out);
}